// round 3
// baseline (speedup 1.0000x reference)
#include <cuda_runtime.h>
#include <cuda_bf16.h>
#include <cstdint>

// Problem constants
static constexpr int BB  = 8192;   // batch
static constexpr int DK  = 1024;   // embedding dim
static constexpr int NT  = 64;     // 8192 / 128 tiles per side
static constexpr int NCH = 16;     // 1024 / 64 K-chunks
static constexpr float INV_T = 20.0f;      // 1 / 0.05
static constexpr float HNW_SCALE = 1.5f;   // 1 + hard_negative_weight

static constexpr int STAGE_BYTES = 32768;            // A(16K) + B(16K) bf16
static constexpr int TILE_PAD    = 129;              // fp32 tile row pad
static constexpr int SMEM_BYTES  = 3 * STAGE_BYTES;  // 98304 >= 128*129*4 (66048)

// ------------------------- device scratch (static, no allocs) -------------------------
__device__ __align__(256) __nv_bfloat16 g_Ibf[(size_t)BB * DK];
__device__ __align__(256) __nv_bfloat16 g_Sbf[(size_t)BB * DK];
__device__ float g_rowMax[NT * BB];
__device__ float g_rowSum[NT * BB];
__device__ float g_rowHn [NT * BB];
__device__ float g_colMax[NT * BB];
__device__ float g_colSum[NT * BB];
__device__ float g_colHn [NT * BB];
__device__ float g_diag  [BB];
__device__ float g_loss  [2 * BB];

// ------------------------- helpers -------------------------
static __device__ __forceinline__ uint32_t smem_u32(const void* p) {
    uint32_t a;
    asm("{ .reg .u64 t; cvta.to.shared.u64 t, %1; cvt.u32.u64 %0, t; }" : "=r"(a) : "l"(p));
    return a;
}
static __device__ __forceinline__ void cp16(uint32_t s, const void* g) {
    asm volatile("cp.async.cg.shared.global [%0], [%1], 16;" :: "r"(s), "l"(g) : "memory");
}
// Swizzled smem addr for a [128][64-bf16] tile, 128B/row, 16B chunks xor'd by row&7
static __device__ __forceinline__ uint32_t sw_addr(uint32_t base, int row, int kchunk) {
    return base + (uint32_t)(row * 128) + (uint32_t)(((kchunk ^ (row & 7)) << 4));
}
static __device__ __forceinline__ void ldsm_x4(uint32_t& r0, uint32_t& r1, uint32_t& r2,
                                               uint32_t& r3, uint32_t addr) {
    asm volatile("ldmatrix.sync.aligned.m8n8.x4.shared.b16 {%0,%1,%2,%3}, [%4];"
                 : "=r"(r0), "=r"(r1), "=r"(r2), "=r"(r3) : "r"(addr));
}
static __device__ __forceinline__ void mma16816(float& c0, float& c1, float& c2, float& c3,
                                                uint32_t a0, uint32_t a1, uint32_t a2,
                                                uint32_t a3, uint32_t b0, uint32_t b1) {
    asm volatile(
        "mma.sync.aligned.m16n8k16.row.col.f32.bf16.bf16.f32 "
        "{%0,%1,%2,%3}, {%4,%5,%6,%7}, {%8,%9}, {%0,%1,%2,%3};"
        : "+f"(c0), "+f"(c1), "+f"(c2), "+f"(c3)
        : "r"(a0), "r"(a1), "r"(a2), "r"(a3), "r"(b0), "r"(b1));
}

// ------------------------- kernel 1: fp32 -> bf16 convert -------------------------
__global__ void convert_kernel(const float* __restrict__ I, const float* __restrict__ S) {
    const uint32_t n4 = (uint32_t)(BB * DK) / 4u;  // 2,097,152 float4 per matrix
    uint32_t i = blockIdx.x * blockDim.x + threadIdx.x;
    const float4* src;
    __nv_bfloat16* dst;
    uint32_t j;
    if (i < n4) { src = (const float4*)I; dst = g_Ibf; j = i; }
    else        { src = (const float4*)S; dst = g_Sbf; j = i - n4; }
    float4 v = src[j];
    __nv_bfloat162 h0, h1;
    h0.x = __float2bfloat16(v.x); h0.y = __float2bfloat16(v.y);
    h1.x = __float2bfloat16(v.z); h1.y = __float2bfloat16(v.w);
    ((__nv_bfloat162*)dst)[2 * j]     = h0;
    ((__nv_bfloat162*)dst)[2 * j + 1] = h1;
}

// ------------------------- kernel 2: GEMM tile + fused reductions -------------------------
// 256 threads, warp grid 4(M) x 2(N); warp tile 32x64; mma m16n8k16.
static __device__ __forceinline__ void load_chunk(int tid, const __nv_bfloat16* Ap,
                                                  const __nv_bfloat16* Bp,
                                                  uint32_t DATA, int kc) {
    int s = kc % 3;
    uint32_t abase = DATA + (uint32_t)s * STAGE_BYTES;
    uint32_t bbase = abase + 16384u;
    const __nv_bfloat16* ga0 = Ap + kc * 64;
    const __nv_bfloat16* gb0 = Bp + kc * 64;
#pragma unroll
    for (int i = 0; i < 4; i++) {
        int v = tid + i * 256;
        int row = v >> 3, cv = v & 7;
        cp16(sw_addr(abase, row, cv), ga0 + (size_t)row * DK + cv * 8);
        cp16(sw_addr(bbase, row, cv), gb0 + (size_t)row * DK + cv * 8);
    }
}

__global__ void __launch_bounds__(256) gemm_kernel() {
    extern __shared__ char smem[];
    const uint32_t DATA = smem_u32(smem);
    const int tid = threadIdx.x, wid = tid >> 5, lane = tid & 31;
    const int wm = wid >> 1, wn = wid & 1;   // 4 x 2 warp grid
    const int bx = blockIdx.x, by = blockIdx.y;

    const __nv_bfloat16* Ap = g_Ibf + (size_t)by * 128 * DK;
    const __nv_bfloat16* Bp = g_Sbf + (size_t)bx * 128 * DK;

    float acc[2][8][4];
#pragma unroll
    for (int mt = 0; mt < 2; mt++)
#pragma unroll
        for (int nt = 0; nt < 8; nt++)
#pragma unroll
            for (int q = 0; q < 4; q++) acc[mt][nt][q] = 0.f;

    // prologue: 3 stages in flight
    load_chunk(tid, Ap, Bp, DATA, 0);
    asm volatile("cp.async.commit_group;" ::: "memory");
    load_chunk(tid, Ap, Bp, DATA, 1);
    asm volatile("cp.async.commit_group;" ::: "memory");
    load_chunk(tid, Ap, Bp, DATA, 2);
    asm volatile("cp.async.commit_group;" ::: "memory");

    for (int k = 0; k < NCH; k++) {
        asm volatile("cp.async.wait_group 2;" ::: "memory");
        __syncthreads();
        int s = k % 3;
        uint32_t abase = DATA + (uint32_t)s * STAGE_BYTES;
        uint32_t bbase = abase + 16384u;
#pragma unroll
        for (int kk = 0; kk < 4; kk++) {
            // A fragments: two m16 tiles
            uint32_t a[2][4];
#pragma unroll
            for (int mt = 0; mt < 2; mt++) {
                int row = wm * 32 + mt * 16 + (lane & 15);
                int kch = 2 * kk + (lane >> 4);
                ldsm_x4(a[mt][0], a[mt][1], a[mt][2], a[mt][3], sw_addr(abase, row, kch));
            }
            // B fragments: 8 n8 tiles via 4 x4-ldmatrix (2 tiles each)
            uint32_t b[8][2];
#pragma unroll
            for (int np = 0; np < 4; np++) {
                int nrow = wn * 64 + np * 16 + (lane & 7) + ((lane >> 4) << 3);
                int kch = 2 * kk + ((lane >> 3) & 1);
                uint32_t r0, r1, r2, r3;
                ldsm_x4(r0, r1, r2, r3, sw_addr(bbase, nrow, kch));
                b[2 * np][0] = r0; b[2 * np][1] = r1;
                b[2 * np + 1][0] = r2; b[2 * np + 1][1] = r3;
            }
#pragma unroll
            for (int mt = 0; mt < 2; mt++)
#pragma unroll
                for (int nt = 0; nt < 8; nt++)
                    mma16816(acc[mt][nt][0], acc[mt][nt][1], acc[mt][nt][2], acc[mt][nt][3],
                             a[mt][0], a[mt][1], a[mt][2], a[mt][3], b[nt][0], b[nt][1]);
        }
        __syncthreads();
        if (k + 3 < NCH) load_chunk(tid, Ap, Bp, DATA, k + 3);
        asm volatile("cp.async.commit_group;" ::: "memory");  // empty groups keep accounting uniform
    }
    asm volatile("cp.async.wait_group 0;" ::: "memory");
    __syncthreads();   // all warps done with pipeline smem -> reuse as fp32 tile

    // scatter accum -> smem fp32 tile (scaled by 1/T)
    float* tile = (float*)smem;
    {
        const int r0 = wm * 32 + (lane >> 2);
        const int c0base = wn * 64 + 2 * (lane & 3);
#pragma unroll
        for (int mt = 0; mt < 2; mt++) {
#pragma unroll
            for (int nt = 0; nt < 8; nt++) {
                int r = r0 + mt * 16;
                int c = c0base + nt * 8;
                tile[r * TILE_PAD + c]           = acc[mt][nt][0] * INV_T;
                tile[r * TILE_PAD + c + 1]       = acc[mt][nt][1] * INV_T;
                tile[(r + 8) * TILE_PAD + c]     = acc[mt][nt][2] * INV_T;
                tile[(r + 8) * TILE_PAD + c + 1] = acc[mt][nt][3] * INV_T;
            }
        }
    }
    __syncthreads();

    const bool dT = (bx == by);
    if (tid < 128) {   // row-side partials (one thread per row)
        int t = tid;
        float m = -3.4e38f, h = -3.4e38f;
#pragma unroll 8
        for (int c = 0; c < 128; c++) {
            float x = tile[t * TILE_PAD + c];
            m = fmaxf(m, x);
            if (!(dT && c == t)) h = fmaxf(h, x);
        }
        float ssum = 0.f;
#pragma unroll 8
        for (int c = 0; c < 128; c++) ssum += __expf(tile[t * TILE_PAD + c] - m);
        int rg = by * 128 + t;
        g_rowMax[bx * BB + rg] = m;
        g_rowSum[bx * BB + rg] = ssum;
        g_rowHn [bx * BB + rg] = h;
        if (dT) g_diag[rg] = tile[t * TILE_PAD + t];
    } else {           // col-side partials (one thread per col)
        int t = tid - 128;
        float m = -3.4e38f, h = -3.4e38f;
#pragma unroll 8
        for (int rr = 0; rr < 128; rr++) {
            float x = tile[rr * TILE_PAD + t];
            m = fmaxf(m, x);
            if (!(dT && rr == t)) h = fmaxf(h, x);
        }
        float ssum = 0.f;
#pragma unroll 8
        for (int rr = 0; rr < 128; rr++) ssum += __expf(tile[rr * TILE_PAD + t] - m);
        int cg = bx * 128 + t;
        g_colMax[by * BB + cg] = m;
        g_colSum[by * BB + cg] = ssum;
        g_colHn [by * BB + cg] = h;
    }
}

// ------------------------- kernel 3: merge partials -> per-row/col loss -------------------------
__global__ void combine_kernel() {
    int i = blockIdx.x * blockDim.x + threadIdx.x;  // 0 .. 2*BB-1
    int idx = i & (BB - 1);
    const float *PM, *PS, *PH;
    if (i < BB) { PM = g_rowMax; PS = g_rowSum; PH = g_rowHn; }
    else        { PM = g_colMax; PS = g_colSum; PH = g_colHn; }

    float m = -3.4e38f, h = -3.4e38f;
#pragma unroll 8
    for (int t = 0; t < NT; t++) {
        m = fmaxf(m, PM[t * BB + idx]);
        h = fmaxf(h, PH[t * BB + idx]);
    }
    float s = 0.f;
#pragma unroll 8
    for (int t = 0; t < NT; t++)
        s += PS[t * BB + idx] * __expf(PM[t * BB + idx] - m);

    float d = g_diag[idx];
    float loss;
    if (h > 0.f) {
        // hard negative is the off-diag max; scale it by 1.5
        float M = fmaxf(m, HNW_SCALE * h);
        float S = s * __expf(m - M) - __expf(h - M) + __expf(HNW_SCALE * h - M);
        loss = M + __logf(S) - d;
    } else {
        // masked argmax lands on the zeroed diagonal -> diagonal gets scaled (matches ref)
        float dd = HNW_SCALE * d;
        float snd = s - __expf(d - m);
        float M = fmaxf(h, dd);
        float S = snd * __expf(m - M) + __expf(dd - M);
        loss = M + __logf(S) - dd;
    }
    g_loss[i] = loss;
}

// ------------------------- kernel 4: deterministic reduction -------------------------
__global__ void finalize_kernel(float* out) {
    __shared__ float red[256];
    float s = 0.f;
    for (int i = threadIdx.x; i < 2 * BB; i += 256) s += g_loss[i];
    red[threadIdx.x] = s;
    __syncthreads();
    for (int o = 128; o > 0; o >>= 1) {
        if (threadIdx.x < (unsigned)o) red[threadIdx.x] += red[threadIdx.x + o];
        __syncthreads();
    }
    if (threadIdx.x == 0) out[0] = red[0] / (float)(2 * BB);
}

// ------------------------- launch -------------------------
extern "C" void kernel_launch(void* const* d_in, const int* in_sizes, int n_in,
                              void* d_out, int out_size) {
    const float* I = (const float*)d_in[0];
    const float* S = (const float*)d_in[1];
    float* out = (float*)d_out;

    cudaFuncSetAttribute(gemm_kernel, cudaFuncAttributeMaxDynamicSharedMemorySize, SMEM_BYTES);

    convert_kernel<<<16384, 256>>>(I, S);
    gemm_kernel<<<dim3(NT, NT, 1), 256, SMEM_BYTES>>>();
    combine_kernel<<<(2 * BB) / 256, 256>>>();
    finalize_kernel<<<1, 256>>>(out);
}